// round 11
// baseline (speedup 1.0000x reference)
#include <cuda_runtime.h>
#include <cuda_fp16.h>
#include <cstdint>
#include <cstddef>

#define IN_CH   12
#define STEP    4
#define UPLAG   2048
#define HIDDEN  1024
#define OUTPUT  256
#define BATCH   2048
#define FEAT    (UPLAG / STEP)        // 512
#define D_IN    (IN_CH * FEAT)        // 6144

// ---------------- scratch (device globals; no allocations allowed) ----------
__device__ __half g_Ahi[BATCH * D_IN];
__device__ __half g_Alo[BATCH * D_IN];
__device__ __half g_B2h[HIDDEN * D_IN];    // W2^T, single fp16 term
__device__ __half g_Hhi[BATCH * HIDDEN];
__device__ __half g_Hlo[BATCH * HIDDEN];
__device__ __half g_B3h[OUTPUT * HIDDEN];  // W3^T hi
__device__ __half g_B3l[OUTPUT * HIDDEN];  // W3^T lo

// ---------------- helpers ----------------------------------------------------
__device__ __forceinline__ uint32_t smem_u32(const void* p) {
    uint32_t a;
    asm("{ .reg .u64 t; cvta.to.shared.u64 t, %1; cvt.u32.u64 %0, t; }"
        : "=r"(a) : "l"(p));
    return a;
}
__device__ __forceinline__ void cp_async16(uint32_t dst, const void* src) {
    asm volatile("cp.async.cg.shared.global [%0], [%1], 16;" :: "r"(dst), "l"(src) : "memory");
}
__device__ __forceinline__ void cp_commit() {
    asm volatile("cp.async.commit_group;" ::: "memory");
}
template<int N>
__device__ __forceinline__ void cp_wait() {
    asm volatile("cp.async.wait_group %0;" :: "n"(N) : "memory");
}
__device__ __forceinline__ void ldm_x4(uint32_t* r, uint32_t addr) {
    asm volatile("ldmatrix.sync.aligned.m8n8.x4.shared.b16 {%0,%1,%2,%3}, [%4];"
                 : "=r"(r[0]), "=r"(r[1]), "=r"(r[2]), "=r"(r[3]) : "r"(addr));
}
__device__ __forceinline__ void mma_fp16(float* c, const uint32_t* a, const uint32_t* b) {
    asm volatile(
        "mma.sync.aligned.m16n8k16.row.col.f32.f16.f16.f32 "
        "{%0,%1,%2,%3}, {%4,%5,%6,%7}, {%8,%9}, {%0,%1,%2,%3};"
        : "+f"(c[0]), "+f"(c[1]), "+f"(c[2]), "+f"(c[3])
        : "r"(a[0]), "r"(a[1]), "r"(a[2]), "r"(a[3]), "r"(b[0]), "r"(b[1]));
}

// ---------------------------------------------------------------------------
// conv + fp16 split: 4 patches per thread, 8B vector stores
// ---------------------------------------------------------------------------
__global__ void conv_split_kernel(const float* __restrict__ x,
                                  const float* __restrict__ W1,
                                  const float* __restrict__ b1,
                                  __half* __restrict__ ahi,
                                  __half* __restrict__ alo) {
    int idx = blockIdx.x * blockDim.x + threadIdx.x;
    const int total4 = BATCH * IN_CH * FEAT / 4;
    if (idx >= total4) return;
    int c = (idx >> 7) % IN_CH;
    float4 w = reinterpret_cast<const float4*>(W1)[c];
    float bb = b1[c];
    const float4* src = reinterpret_cast<const float4*>(x) + (size_t)idx * 4;
    union { __half b[4]; uint2 u; } H, L;
#pragma unroll
    for (int j = 0; j < 4; j++) {
        float4 v = src[j];
        float r = fmaf(v.x, w.x, fmaf(v.y, w.y, fmaf(v.z, w.z, fmaf(v.w, w.w, bb))));
        H.b[j] = __float2half(r);
        L.b[j] = __float2half(r - __half2float(H.b[j]));
    }
    reinterpret_cast<uint2*>(ahi)[idx] = H.u;
    reinterpret_cast<uint2*>(alo)[idx] = L.u;
}

// ---------------------------------------------------------------------------
// transpose + fp16 split:  W[K,N] f32 -> hi (+optional lo) [N,K] fp16
// ---------------------------------------------------------------------------
__global__ void transpose_split_kernel(const float* __restrict__ W,
                                       __half* __restrict__ hi,
                                       __half* __restrict__ lo,
                                       int K, int N) {
    __shared__ float t[32][33];
    int n0 = blockIdx.x * 32, k0 = blockIdx.y * 32;
    int tx = threadIdx.x, ty = threadIdx.y;
#pragma unroll
    for (int j = 0; j < 32; j += 8)
        t[ty + j][tx] = W[(size_t)(k0 + ty + j) * N + n0 + tx];
    __syncthreads();
#pragma unroll
    for (int j = 0; j < 32; j += 8) {
        float v = t[tx][ty + j];
        __half h = __float2half(v);
        size_t o = (size_t)(n0 + ty + j) * K + k0 + tx;
        hi[o] = h;
        if (lo) lo[o] = __float2half(v - __half2float(h));
    }
}

// ---------------------------------------------------------------------------
// split-fp16 HMMA GEMM.
//   NPROD=2: C = act((Ah+Al)[M,K] @ Bh^T + bias)          (B single fp16)
//   NPROD=3: C = act((Ah+Al)     @ (Bh+Bl)^T + bias)
// Per-half fragment loads (register-lean), 1 barrier per iteration.
// ---------------------------------------------------------------------------
#define BK       32
#define ROWB     80

template<int KDIM, int BM, int BN, int WARPS_M, int WARPS_N,
         int WM_TILES, int WN_TILES, int NPROD, bool SPLIT_OUT, int MAXCTA, int NSTAGE>
__global__ __launch_bounds__(WARPS_M * WARPS_N * 32, MAXCTA)
void gemm_hmma(const __half* __restrict__ Ahi, const __half* __restrict__ Alo,
               const __half* __restrict__ Bhi, const __half* __restrict__ Blo,
               const float* __restrict__ bias,
               __half* __restrict__ Ohi, __half* __restrict__ Olo,
               float* __restrict__ Of32, int Nglob) {
    constexpr int THREADS = WARPS_M * WARPS_N * 32;
    constexpr int NBT = (NPROD == 3) ? 2 : 1;     // B tiles per stage
    constexpr int TA = BM * ROWB;
    constexpr int TB = BN * ROWB;
    constexpr int STAGE_BYTES = 2 * TA + NBT * TB;
    constexpr int NCHUNK = (2 * BM + NBT * BN) * 4;
    constexpr int NIT = KDIM / BK;

    extern __shared__ char smem[];
    const uint32_t sb = smem_u32(smem);

    const int tid = threadIdx.x;
    const int wid = tid / 32;
    const int lane = tid % 32;
    const int g = lane >> 2;
    const int tg = lane & 3;
    const int brow = blockIdx.y * BM;
    const int bcol = blockIdx.x * BN;
    const int wm = (wid / WARPS_N) * (WM_TILES * 16);
    const int wn = (wid % WARPS_N) * (WN_TILES * 8);

    const int sub = lane >> 3;
    const int r8  = lane & 7;
    const int a_row = ((sub & 1) << 3) + r8;
    const int a_k   = (sub >> 1) << 3;
    const int b_row = ((sub >> 1) << 3) + r8;
    const int b_k   = (sub & 1) << 3;

    float acc[WM_TILES][WN_TILES][4];
#pragma unroll
    for (int i = 0; i < WM_TILES; i++)
#pragma unroll
        for (int j = 0; j < WN_TILES; j++)
#pragma unroll
            for (int q = 0; q < 4; q++) acc[i][j][q] = 0.0f;

    auto load_stage = [&](int buf, int kt) {
        const int k0 = kt * BK;
        const uint32_t base = sb + buf * STAGE_BYTES;
#pragma unroll
        for (int t = tid; t < NCHUNK; t += THREADS) {
            int chunk = t & 3;
            int rr = t >> 2;
            const __half* src;
            uint32_t dst;
            if (rr < BM) {
                src = Ahi + (size_t)(brow + rr) * KDIM + k0 + chunk * 8;
                dst = base + rr * ROWB + chunk * 16;
            } else if (rr < 2 * BM) {
                int r = rr - BM;
                src = Alo + (size_t)(brow + r) * KDIM + k0 + chunk * 8;
                dst = base + TA + r * ROWB + chunk * 16;
            } else if (rr < 2 * BM + BN) {
                int r = rr - 2 * BM;
                src = Bhi + (size_t)(bcol + r) * KDIM + k0 + chunk * 8;
                dst = base + 2 * TA + r * ROWB + chunk * 16;
            } else {
                int r = rr - 2 * BM - BN;
                src = Blo + (size_t)(bcol + r) * KDIM + k0 + chunk * 8;
                dst = base + 2 * TA + TB + r * ROWB + chunk * 16;
            }
            cp_async16(dst, src);
        }
    };

#pragma unroll
    for (int s = 0; s < NSTAGE - 1; s++) { load_stage(s, s); cp_commit(); }

    for (int it = 0; it < NIT; it++) {
        cp_wait<NSTAGE - 2>();
        __syncthreads();
        if (it + NSTAGE - 1 < NIT) load_stage((it + NSTAGE - 1) % NSTAGE, it + NSTAGE - 1);
        cp_commit();

        const uint32_t sbase = sb + (it % NSTAGE) * STAGE_BYTES;
        const uint32_t pAh = sbase;
        const uint32_t pAl = sbase + TA;
        const uint32_t pBh = sbase + 2 * TA;
        const uint32_t pBl = sbase + 2 * TA + TB;

#pragma unroll
        for (int h = 0; h < 2; h++) {
            const int kk = h * 16;
            uint32_t ah[WM_TILES][4], al[WM_TILES][4];
            uint32_t bh[WN_TILES][2], bl[WN_TILES][2];
#pragma unroll
            for (int mt = 0; mt < WM_TILES; mt++) {
                uint32_t ra = (uint32_t)(wm + mt * 16 + a_row) * ROWB + (kk + a_k) * 2;
                ldm_x4(ah[mt], pAh + ra);
                ldm_x4(al[mt], pAl + ra);
            }
#pragma unroll
            for (int nt = 0; nt < WN_TILES; nt += 2) {
                uint32_t rb = (uint32_t)(wn + nt * 8 + b_row) * ROWB + (kk + b_k) * 2;
                ldm_x4(&bh[nt][0], pBh + rb);
                if (NPROD == 3) ldm_x4(&bl[nt][0], pBl + rb);
            }
            // product-outer ordering: consecutive MMAs hit different accumulators
#pragma unroll
            for (int mt = 0; mt < WM_TILES; mt++)
#pragma unroll
                for (int nt = 0; nt < WN_TILES; nt++)
                    mma_fp16(acc[mt][nt], ah[mt], bh[nt]);
#pragma unroll
            for (int mt = 0; mt < WM_TILES; mt++)
#pragma unroll
                for (int nt = 0; nt < WN_TILES; nt++)
                    mma_fp16(acc[mt][nt], al[mt], bh[nt]);
            if (NPROD == 3) {
#pragma unroll
                for (int mt = 0; mt < WM_TILES; mt++)
#pragma unroll
                    for (int nt = 0; nt < WN_TILES; nt++)
                        mma_fp16(acc[mt][nt], ah[mt], bl[nt]);
            }
        }
    }

    // ---------------- epilogue ----------------------------------------------
#pragma unroll
    for (int mt = 0; mt < WM_TILES; mt++) {
#pragma unroll
        for (int nt = 0; nt < WN_TILES; nt++) {
            int row = brow + wm + mt * 16 + g;
            int col = bcol + wn + nt * 8 + tg * 2;
            float b0 = bias[col], b1v = bias[col + 1];
            if (SPLIT_OUT) {
                float v0 = fmaxf(acc[mt][nt][0] + b0, 0.0f);
                float v1 = fmaxf(acc[mt][nt][1] + b1v, 0.0f);
                float v2 = fmaxf(acc[mt][nt][2] + b0, 0.0f);
                float v3 = fmaxf(acc[mt][nt][3] + b1v, 0.0f);
                __half h0 = __float2half(v0), h1 = __float2half(v1);
                __half h2 = __float2half(v2), h3 = __float2half(v3);
                __half2 hi01{h0, h1}, hi23{h2, h3};
                __half2 lo01{__float2half(v0 - __half2float(h0)),
                             __float2half(v1 - __half2float(h1))};
                __half2 lo23{__float2half(v2 - __half2float(h2)),
                             __float2half(v3 - __half2float(h3))};
                *reinterpret_cast<__half2*>(&Ohi[(size_t)row * Nglob + col]) = hi01;
                *reinterpret_cast<__half2*>(&Olo[(size_t)row * Nglob + col]) = lo01;
                *reinterpret_cast<__half2*>(&Ohi[(size_t)(row + 8) * Nglob + col]) = hi23;
                *reinterpret_cast<__half2*>(&Olo[(size_t)(row + 8) * Nglob + col]) = lo23;
            } else {
                float2 v01{acc[mt][nt][0] + b0, acc[mt][nt][1] + b1v};
                float2 v23{acc[mt][nt][2] + b0, acc[mt][nt][3] + b1v};
                *reinterpret_cast<float2*>(&Of32[(size_t)row * Nglob + col]) = v01;
                *reinterpret_cast<float2*>(&Of32[(size_t)(row + 8) * Nglob + col]) = v23;
            }
        }
    }
}

// ---------------------------------------------------------------------------
extern "C" void kernel_launch(void* const* d_in, const int* in_sizes, int n_in,
                              void* d_out, int out_size) {
    const float* x  = (const float*)d_in[0];
    const float* W1 = (const float*)d_in[1];
    const float* b1 = (const float*)d_in[2];
    const float* W2 = (const float*)d_in[3];
    const float* b2 = (const float*)d_in[4];
    const float* W3 = (const float*)d_in[5];
    const float* b3 = (const float*)d_in[6];
    float* out = (float*)d_out;

    __half *Ahi, *Alo, *B2h, *Hhi, *Hlo, *B3h, *B3l;
    cudaGetSymbolAddress((void**)&Ahi, g_Ahi);
    cudaGetSymbolAddress((void**)&Alo, g_Alo);
    cudaGetSymbolAddress((void**)&B2h, g_B2h);
    cudaGetSymbolAddress((void**)&Hhi, g_Hhi);
    cudaGetSymbolAddress((void**)&Hlo, g_Hlo);
    cudaGetSymbolAddress((void**)&B3h, g_B3h);
    cudaGetSymbolAddress((void**)&B3l, g_B3l);

    // GEMM1: 2-product, 64x64 tile, 8 warps (2x4), warp tile 32x16, 4 stages
    //        grid 16x32 = 512 CTAs, 3 CTAs/SM (smem 61.4KB, regs<=85)
    constexpr int SMEM1 = 4 * (2 * 64 * ROWB + 1 * 64 * ROWB);     // 61440
    // GEMM2: 3-product, 64x32 tile, 4 warps, 3 stages -> 256 CTAs, 4 CTAs/SM
    constexpr int SMEM2 = 3 * (2 * 64 * ROWB + 2 * 32 * ROWB);     // 46080

    cudaFuncSetAttribute((const void*)gemm_hmma<D_IN, 64, 64, 2, 4, 2, 2, 2, true, 3, 4>,
                         cudaFuncAttributeMaxDynamicSharedMemorySize, SMEM1);
    cudaFuncSetAttribute((const void*)gemm_hmma<HIDDEN, 64, 32, 2, 2, 2, 2, 3, false, 4, 3>,
                         cudaFuncAttributeMaxDynamicSharedMemorySize, SMEM2);

    // 1) conv + split (fp16 hi/lo)
    {
        int total4 = BATCH * IN_CH * FEAT / 4;
        conv_split_kernel<<<(total4 + 255) / 256, 256>>>(x, W1, b1, Ahi, Alo);
    }
    // 2) weight transposes: W2 -> single fp16; W3 -> fp16 hi+lo
    transpose_split_kernel<<<dim3(HIDDEN / 32, D_IN / 32), dim3(32, 8)>>>(W2, B2h, nullptr, D_IN, HIDDEN);
    transpose_split_kernel<<<dim3(OUTPUT / 32, HIDDEN / 32), dim3(32, 8)>>>(W3, B3h, B3l, HIDDEN, OUTPUT);

    // 3) GEMM1 (2 products) + relu -> split h   [2048,6144]x[6144,1024]
    gemm_hmma<D_IN, 64, 64, 2, 4, 2, 2, 2, true, 3, 4>
        <<<dim3(HIDDEN / 64, BATCH / 64), 256, SMEM1>>>(
            Ahi, Alo, B2h, nullptr, b2, Hhi, Hlo, nullptr, HIDDEN);

    // 4) GEMM2 (3 products) -> fp32 out         [2048,1024]x[1024,256]
    gemm_hmma<HIDDEN, 64, 32, 2, 2, 2, 2, 3, false, 4, 3>
        <<<dim3(OUTPUT / 32, BATCH / 64), 128, SMEM2>>>(
            Hhi, Hlo, B3h, B3l, b3, nullptr, nullptr, out, OUTPUT);
}

// round 12
// speedup vs baseline: 1.1320x; 1.1320x over previous
#include <cuda_runtime.h>
#include <cuda_fp16.h>
#include <cstdint>
#include <cstddef>

#define IN_CH   12
#define STEP    4
#define UPLAG   2048
#define HIDDEN  1024
#define OUTPUT  256
#define BATCH   2048
#define FEAT    (UPLAG / STEP)        // 512
#define D_IN    (IN_CH * FEAT)        // 6144

// ---------------- scratch (device globals; no allocations allowed) ----------
__device__ __half g_Ahi[BATCH * D_IN];
__device__ __half g_Alo[BATCH * D_IN];
__device__ __half g_B2h[HIDDEN * D_IN];    // W2^T, single fp16 term
__device__ __half g_Hhi[BATCH * HIDDEN];
__device__ __half g_Hlo[BATCH * HIDDEN];
__device__ __half g_B3h[OUTPUT * HIDDEN];  // W3^T hi
__device__ __half g_B3l[OUTPUT * HIDDEN];  // W3^T lo

// ---------------- helpers ----------------------------------------------------
__device__ __forceinline__ uint32_t smem_u32(const void* p) {
    uint32_t a;
    asm("{ .reg .u64 t; cvta.to.shared.u64 t, %1; cvt.u32.u64 %0, t; }"
        : "=r"(a) : "l"(p));
    return a;
}
__device__ __forceinline__ void cp_async16(uint32_t dst, const void* src) {
    asm volatile("cp.async.cg.shared.global [%0], [%1], 16;" :: "r"(dst), "l"(src) : "memory");
}
__device__ __forceinline__ void cp_commit() {
    asm volatile("cp.async.commit_group;" ::: "memory");
}
template<int N>
__device__ __forceinline__ void cp_wait() {
    asm volatile("cp.async.wait_group %0;" :: "n"(N) : "memory");
}
__device__ __forceinline__ void ldm_x4(uint32_t* r, uint32_t addr) {
    asm volatile("ldmatrix.sync.aligned.m8n8.x4.shared.b16 {%0,%1,%2,%3}, [%4];"
                 : "=r"(r[0]), "=r"(r[1]), "=r"(r[2]), "=r"(r[3]) : "r"(addr));
}
__device__ __forceinline__ void mma_fp16(float* c, const uint32_t* a, const uint32_t* b) {
    asm volatile(
        "mma.sync.aligned.m16n8k16.row.col.f32.f16.f16.f32 "
        "{%0,%1,%2,%3}, {%4,%5,%6,%7}, {%8,%9}, {%0,%1,%2,%3};"
        : "+f"(c[0]), "+f"(c[1]), "+f"(c[2]), "+f"(c[3])
        : "r"(a[0]), "r"(a[1]), "r"(a[2]), "r"(a[3]), "r"(b[0]), "r"(b[1]));
}

// ---------------------------------------------------------------------------
// conv + fp16 split: 4 patches per thread, 8B vector stores
// ---------------------------------------------------------------------------
__global__ void conv_split_kernel(const float* __restrict__ x,
                                  const float* __restrict__ W1,
                                  const float* __restrict__ b1,
                                  __half* __restrict__ ahi,
                                  __half* __restrict__ alo) {
    int idx = blockIdx.x * blockDim.x + threadIdx.x;
    const int total4 = BATCH * IN_CH * FEAT / 4;
    if (idx >= total4) return;
    int c = (idx >> 7) % IN_CH;
    float4 w = reinterpret_cast<const float4*>(W1)[c];
    float bb = b1[c];
    const float4* src = reinterpret_cast<const float4*>(x) + (size_t)idx * 4;
    union { __half b[4]; uint2 u; } H, L;
#pragma unroll
    for (int j = 0; j < 4; j++) {
        float4 v = src[j];
        float r = fmaf(v.x, w.x, fmaf(v.y, w.y, fmaf(v.z, w.z, fmaf(v.w, w.w, bb))));
        H.b[j] = __float2half(r);
        L.b[j] = __float2half(r - __half2float(H.b[j]));
    }
    reinterpret_cast<uint2*>(ahi)[idx] = H.u;
    reinterpret_cast<uint2*>(alo)[idx] = L.u;
}

// ---------------------------------------------------------------------------
// transpose + fp16 split:  W[K,N] f32 -> hi (+optional lo) [N,K] fp16
// ---------------------------------------------------------------------------
__global__ void transpose_split_kernel(const float* __restrict__ W,
                                       __half* __restrict__ hi,
                                       __half* __restrict__ lo,
                                       int K, int N) {
    __shared__ float t[32][33];
    int n0 = blockIdx.x * 32, k0 = blockIdx.y * 32;
    int tx = threadIdx.x, ty = threadIdx.y;
#pragma unroll
    for (int j = 0; j < 32; j += 8)
        t[ty + j][tx] = W[(size_t)(k0 + ty + j) * N + n0 + tx];
    __syncthreads();
#pragma unroll
    for (int j = 0; j < 32; j += 8) {
        float v = t[tx][ty + j];
        __half h = __float2half(v);
        size_t o = (size_t)(n0 + ty + j) * K + k0 + tx;
        hi[o] = h;
        if (lo) lo[o] = __float2half(v - __half2float(h));
    }
}

// ---------------------------------------------------------------------------
// split-fp16 HMMA GEMM.
//   NPROD=2: C = act((Ah+Al)[M,K] @ Bh^T + bias)          (B single fp16)
//   NPROD=3: C = act((Ah+Al)     @ (Bh+Bl)^T + bias)
// Per-half fragment loads, 1 barrier per iteration.
// ---------------------------------------------------------------------------
#define BK       32
#define ROWB     80

template<int KDIM, int BM, int BN, int WARPS_M, int WARPS_N,
         int WM_TILES, int WN_TILES, int NPROD, bool SPLIT_OUT, int MAXCTA, int NSTAGE>
__global__ __launch_bounds__(WARPS_M * WARPS_N * 32, MAXCTA)
void gemm_hmma(const __half* __restrict__ Ahi, const __half* __restrict__ Alo,
               const __half* __restrict__ Bhi, const __half* __restrict__ Blo,
               const float* __restrict__ bias,
               __half* __restrict__ Ohi, __half* __restrict__ Olo,
               float* __restrict__ Of32, int Nglob) {
    constexpr int THREADS = WARPS_M * WARPS_N * 32;
    constexpr int NBT = (NPROD == 3) ? 2 : 1;     // B tiles per stage
    constexpr int TA = BM * ROWB;
    constexpr int TB = BN * ROWB;
    constexpr int STAGE_BYTES = 2 * TA + NBT * TB;
    constexpr int NCHUNK = (2 * BM + NBT * BN) * 4;
    constexpr int NIT = KDIM / BK;

    extern __shared__ char smem[];
    const uint32_t sb = smem_u32(smem);

    const int tid = threadIdx.x;
    const int wid = tid / 32;
    const int lane = tid % 32;
    const int g = lane >> 2;
    const int tg = lane & 3;
    const int brow = blockIdx.y * BM;
    const int bcol = blockIdx.x * BN;
    const int wm = (wid / WARPS_N) * (WM_TILES * 16);
    const int wn = (wid % WARPS_N) * (WN_TILES * 8);

    const int sub = lane >> 3;
    const int r8  = lane & 7;
    const int a_row = ((sub & 1) << 3) + r8;
    const int a_k   = (sub >> 1) << 3;
    const int b_row = ((sub >> 1) << 3) + r8;
    const int b_k   = (sub & 1) << 3;

    float acc[WM_TILES][WN_TILES][4];
#pragma unroll
    for (int i = 0; i < WM_TILES; i++)
#pragma unroll
        for (int j = 0; j < WN_TILES; j++)
#pragma unroll
            for (int q = 0; q < 4; q++) acc[i][j][q] = 0.0f;

    auto load_stage = [&](int buf, int kt) {
        const int k0 = kt * BK;
        const uint32_t base = sb + buf * STAGE_BYTES;
#pragma unroll
        for (int t = tid; t < NCHUNK; t += THREADS) {
            int chunk = t & 3;
            int rr = t >> 2;
            const __half* src;
            uint32_t dst;
            if (rr < BM) {
                src = Ahi + (size_t)(brow + rr) * KDIM + k0 + chunk * 8;
                dst = base + rr * ROWB + chunk * 16;
            } else if (rr < 2 * BM) {
                int r = rr - BM;
                src = Alo + (size_t)(brow + r) * KDIM + k0 + chunk * 8;
                dst = base + TA + r * ROWB + chunk * 16;
            } else if (rr < 2 * BM + BN) {
                int r = rr - 2 * BM;
                src = Bhi + (size_t)(bcol + r) * KDIM + k0 + chunk * 8;
                dst = base + 2 * TA + r * ROWB + chunk * 16;
            } else {
                int r = rr - 2 * BM - BN;
                src = Blo + (size_t)(bcol + r) * KDIM + k0 + chunk * 8;
                dst = base + 2 * TA + TB + r * ROWB + chunk * 16;
            }
            cp_async16(dst, src);
        }
    };

#pragma unroll
    for (int s = 0; s < NSTAGE - 1; s++) { load_stage(s, s); cp_commit(); }

    for (int it = 0; it < NIT; it++) {
        cp_wait<NSTAGE - 2>();
        __syncthreads();
        if (it + NSTAGE - 1 < NIT) load_stage((it + NSTAGE - 1) % NSTAGE, it + NSTAGE - 1);
        cp_commit();

        const uint32_t sbase = sb + (it % NSTAGE) * STAGE_BYTES;
        const uint32_t pAh = sbase;
        const uint32_t pAl = sbase + TA;
        const uint32_t pBh = sbase + 2 * TA;
        const uint32_t pBl = sbase + 2 * TA + TB;

#pragma unroll
        for (int h = 0; h < 2; h++) {
            const int kk = h * 16;
            uint32_t ah[WM_TILES][4], al[WM_TILES][4];
            uint32_t bh[WN_TILES][2], bl[WN_TILES][2];
#pragma unroll
            for (int mt = 0; mt < WM_TILES; mt++) {
                uint32_t ra = (uint32_t)(wm + mt * 16 + a_row) * ROWB + (kk + a_k) * 2;
                ldm_x4(ah[mt], pAh + ra);
                ldm_x4(al[mt], pAl + ra);
            }
#pragma unroll
            for (int nt = 0; nt < WN_TILES; nt += 2) {
                uint32_t rb = (uint32_t)(wn + nt * 8 + b_row) * ROWB + (kk + b_k) * 2;
                ldm_x4(&bh[nt][0], pBh + rb);
                if (NPROD == 3) ldm_x4(&bl[nt][0], pBl + rb);
            }
            // product-outer ordering: consecutive MMAs hit different accumulators
#pragma unroll
            for (int mt = 0; mt < WM_TILES; mt++)
#pragma unroll
                for (int nt = 0; nt < WN_TILES; nt++)
                    mma_fp16(acc[mt][nt], ah[mt], bh[nt]);
#pragma unroll
            for (int mt = 0; mt < WM_TILES; mt++)
#pragma unroll
                for (int nt = 0; nt < WN_TILES; nt++)
                    mma_fp16(acc[mt][nt], al[mt], bh[nt]);
            if (NPROD == 3) {
#pragma unroll
                for (int mt = 0; mt < WM_TILES; mt++)
#pragma unroll
                    for (int nt = 0; nt < WN_TILES; nt++)
                        mma_fp16(acc[mt][nt], ah[mt], bl[nt]);
            }
        }
    }

    // ---------------- epilogue ----------------------------------------------
#pragma unroll
    for (int mt = 0; mt < WM_TILES; mt++) {
#pragma unroll
        for (int nt = 0; nt < WN_TILES; nt++) {
            int row = brow + wm + mt * 16 + g;
            int col = bcol + wn + nt * 8 + tg * 2;
            float b0 = bias[col], b1v = bias[col + 1];
            if (SPLIT_OUT) {
                float v0 = fmaxf(acc[mt][nt][0] + b0, 0.0f);
                float v1 = fmaxf(acc[mt][nt][1] + b1v, 0.0f);
                float v2 = fmaxf(acc[mt][nt][2] + b0, 0.0f);
                float v3 = fmaxf(acc[mt][nt][3] + b1v, 0.0f);
                __half h0 = __float2half(v0), h1 = __float2half(v1);
                __half h2 = __float2half(v2), h3 = __float2half(v3);
                __half2 hi01{h0, h1}, hi23{h2, h3};
                __half2 lo01{__float2half(v0 - __half2float(h0)),
                             __float2half(v1 - __half2float(h1))};
                __half2 lo23{__float2half(v2 - __half2float(h2)),
                             __float2half(v3 - __half2float(h3))};
                *reinterpret_cast<__half2*>(&Ohi[(size_t)row * Nglob + col]) = hi01;
                *reinterpret_cast<__half2*>(&Olo[(size_t)row * Nglob + col]) = lo01;
                *reinterpret_cast<__half2*>(&Ohi[(size_t)(row + 8) * Nglob + col]) = hi23;
                *reinterpret_cast<__half2*>(&Olo[(size_t)(row + 8) * Nglob + col]) = lo23;
            } else {
                float2 v01{acc[mt][nt][0] + b0, acc[mt][nt][1] + b1v};
                float2 v23{acc[mt][nt][2] + b0, acc[mt][nt][3] + b1v};
                *reinterpret_cast<float2*>(&Of32[(size_t)row * Nglob + col]) = v01;
                *reinterpret_cast<float2*>(&Of32[(size_t)(row + 8) * Nglob + col]) = v23;
            }
        }
    }
}

// ---------------------------------------------------------------------------
extern "C" void kernel_launch(void* const* d_in, const int* in_sizes, int n_in,
                              void* d_out, int out_size) {
    const float* x  = (const float*)d_in[0];
    const float* W1 = (const float*)d_in[1];
    const float* b1 = (const float*)d_in[2];
    const float* W2 = (const float*)d_in[3];
    const float* b2 = (const float*)d_in[4];
    const float* W3 = (const float*)d_in[5];
    const float* b3 = (const float*)d_in[6];
    float* out = (float*)d_out;

    __half *Ahi, *Alo, *B2h, *Hhi, *Hlo, *B3h, *B3l;
    cudaGetSymbolAddress((void**)&Ahi, g_Ahi);
    cudaGetSymbolAddress((void**)&Alo, g_Alo);
    cudaGetSymbolAddress((void**)&B2h, g_B2h);
    cudaGetSymbolAddress((void**)&Hhi, g_Hhi);
    cudaGetSymbolAddress((void**)&Hlo, g_Hlo);
    cudaGetSymbolAddress((void**)&B3h, g_B3h);
    cudaGetSymbolAddress((void**)&B3l, g_B3l);

    // GEMM1: 2-product, 64x128 CTA tile, 8 warps (2x4), warp tile 32x32,
    //        4 stages (stage 20.5KB, total 81.9KB) -> 256 CTAs, 2 CTAs/SM,
    //        16 warps/SM.  LDSM/MMA = 0.375 -> crossbar no longer binding.
    constexpr int SMEM1 = 4 * (2 * 64 * ROWB + 1 * 128 * ROWB);    // 81920
    // GEMM2: 3-product, 64x32 tile, 4 warps, 3 stages -> 256 CTAs, 4 CTAs/SM
    constexpr int SMEM2 = 3 * (2 * 64 * ROWB + 2 * 32 * ROWB);     // 46080

    cudaFuncSetAttribute((const void*)gemm_hmma<D_IN, 64, 128, 2, 4, 2, 4, 2, true, 2, 4>,
                         cudaFuncAttributeMaxDynamicSharedMemorySize, SMEM1);
    cudaFuncSetAttribute((const void*)gemm_hmma<HIDDEN, 64, 32, 2, 2, 2, 2, 3, false, 4, 3>,
                         cudaFuncAttributeMaxDynamicSharedMemorySize, SMEM2);

    // 1) conv + split (fp16 hi/lo)
    {
        int total4 = BATCH * IN_CH * FEAT / 4;
        conv_split_kernel<<<(total4 + 255) / 256, 256>>>(x, W1, b1, Ahi, Alo);
    }
    // 2) weight transposes: W2 -> single fp16; W3 -> fp16 hi+lo
    transpose_split_kernel<<<dim3(HIDDEN / 32, D_IN / 32), dim3(32, 8)>>>(W2, B2h, nullptr, D_IN, HIDDEN);
    transpose_split_kernel<<<dim3(OUTPUT / 32, HIDDEN / 32), dim3(32, 8)>>>(W3, B3h, B3l, HIDDEN, OUTPUT);

    // 3) GEMM1 (2 products) + relu -> split h   [2048,6144]x[6144,1024]
    gemm_hmma<D_IN, 64, 128, 2, 4, 2, 4, 2, true, 2, 4>
        <<<dim3(HIDDEN / 128, BATCH / 64), 256, SMEM1>>>(
            Ahi, Alo, B2h, nullptr, b2, Hhi, Hlo, nullptr, HIDDEN);

    // 4) GEMM2 (3 products) -> fp32 out         [2048,1024]x[1024,256]
    gemm_hmma<HIDDEN, 64, 32, 2, 2, 2, 2, 3, false, 4, 3>
        <<<dim3(OUTPUT / 32, BATCH / 64), 128, SMEM2>>>(
            Hhi, Hlo, B3h, B3l, b3, nullptr, nullptr, out, OUTPUT);
}

// round 16
// speedup vs baseline: 1.6525x; 1.4598x over previous
#include <cuda_runtime.h>
#include <cuda_fp16.h>
#include <cstdint>
#include <cstddef>

#define IN_CH   12
#define STEP    4
#define UPLAG   2048
#define HIDDEN  1024
#define OUTPUT  256
#define BATCH   2048
#define FEAT    (UPLAG / STEP)        // 512
#define D_IN    (IN_CH * FEAT)        // 6144

// ---------------- scratch (device globals; no allocations allowed) ----------
__device__ __half g_Ah[BATCH * D_IN];      // conv out, single fp16
__device__ __half g_B2h[HIDDEN * D_IN];    // W2^T, single fp16
__device__ __half g_Hhi[BATCH * HIDDEN];
__device__ __half g_Hlo[BATCH * HIDDEN];
__device__ __half g_B3h[OUTPUT * HIDDEN];  // W3^T hi
__device__ __half g_B3l[OUTPUT * HIDDEN];  // W3^T lo

// ---------------- helpers ----------------------------------------------------
__device__ __forceinline__ uint32_t smem_u32(const void* p) {
    uint32_t a;
    asm("{ .reg .u64 t; cvta.to.shared.u64 t, %1; cvt.u32.u64 %0, t; }"
        : "=r"(a) : "l"(p));
    return a;
}
__device__ __forceinline__ void cp_async16(uint32_t dst, const void* src) {
    asm volatile("cp.async.cg.shared.global [%0], [%1], 16;" :: "r"(dst), "l"(src) : "memory");
}
__device__ __forceinline__ void cp_commit() {
    asm volatile("cp.async.commit_group;" ::: "memory");
}
template<int N>
__device__ __forceinline__ void cp_wait() {
    asm volatile("cp.async.wait_group %0;" :: "n"(N) : "memory");
}
__device__ __forceinline__ void ldm_x4(uint32_t* r, uint32_t addr) {
    asm volatile("ldmatrix.sync.aligned.m8n8.x4.shared.b16 {%0,%1,%2,%3}, [%4];"
                 : "=r"(r[0]), "=r"(r[1]), "=r"(r[2]), "=r"(r[3]) : "r"(addr));
}
__device__ __forceinline__ void mma_fp16(float* c, const uint32_t* a, const uint32_t* b) {
    asm volatile(
        "mma.sync.aligned.m16n8k16.row.col.f32.f16.f16.f32 "
        "{%0,%1,%2,%3}, {%4,%5,%6,%7}, {%8,%9}, {%0,%1,%2,%3};"
        : "+f"(c[0]), "+f"(c[1]), "+f"(c[2]), "+f"(c[3])
        : "r"(a[0]), "r"(a[1]), "r"(a[2]), "r"(a[3]), "r"(b[0]), "r"(b[1]));
}

// ---------------------------------------------------------------------------
// conv -> single fp16: 4 patches per thread, 8B vector stores
// ---------------------------------------------------------------------------
__global__ void conv_fp16_kernel(const float* __restrict__ x,
                                 const float* __restrict__ W1,
                                 const float* __restrict__ b1,
                                 __half* __restrict__ ah) {
    int idx = blockIdx.x * blockDim.x + threadIdx.x;
    const int total4 = BATCH * IN_CH * FEAT / 4;
    if (idx >= total4) return;
    int c = (idx >> 7) % IN_CH;
    float4 w = reinterpret_cast<const float4*>(W1)[c];
    float bb = b1[c];
    const float4* src = reinterpret_cast<const float4*>(x) + (size_t)idx * 4;
    union { __half b[4]; uint2 u; } H;
#pragma unroll
    for (int j = 0; j < 4; j++) {
        float4 v = src[j];
        float r = fmaf(v.x, w.x, fmaf(v.y, w.y, fmaf(v.z, w.z, fmaf(v.w, w.w, bb))));
        H.b[j] = __float2half(r);
    }
    reinterpret_cast<uint2*>(ah)[idx] = H.u;
}

// ---------------------------------------------------------------------------
// transpose + fp16 split:  W[K,N] f32 -> hi (+optional lo) [N,K] fp16
// ---------------------------------------------------------------------------
__global__ void transpose_split_kernel(const float* __restrict__ W,
                                       __half* __restrict__ hi,
                                       __half* __restrict__ lo,
                                       int K, int N) {
    __shared__ float t[32][33];
    int n0 = blockIdx.x * 32, k0 = blockIdx.y * 32;
    int tx = threadIdx.x, ty = threadIdx.y;
#pragma unroll
    for (int j = 0; j < 32; j += 8)
        t[ty + j][tx] = W[(size_t)(k0 + ty + j) * N + n0 + tx];
    __syncthreads();
#pragma unroll
    for (int j = 0; j < 32; j += 8) {
        float v = t[tx][ty + j];
        __half h = __float2half(v);
        size_t o = (size_t)(n0 + ty + j) * K + k0 + tx;
        hi[o] = h;
        if (lo) lo[o] = __float2half(v - __half2float(h));
    }
}

// ---------------------------------------------------------------------------
// fp16 HMMA GEMM.
//   NPROD=1: C = act(Ah @ Bh^T + bias)                    (both single fp16)
//   NPROD=2: C = act((Ah+Al) @ Bh^T + bias)
//   NPROD=3: C = act((Ah+Al) @ (Bh+Bl)^T + bias)
// ---------------------------------------------------------------------------
#define BK       32
#define ROWB     80

template<int KDIM, int BM, int BN, int WARPS_M, int WARPS_N,
         int WM_TILES, int WN_TILES, int NPROD, bool SPLIT_OUT, int MAXCTA, int NSTAGE>
__global__ __launch_bounds__(WARPS_M * WARPS_N * 32, MAXCTA)
void gemm_hmma(const __half* __restrict__ Ahi, const __half* __restrict__ Alo,
               const __half* __restrict__ Bhi, const __half* __restrict__ Blo,
               const float* __restrict__ bias,
               __half* __restrict__ Ohi, __half* __restrict__ Olo,
               float* __restrict__ Of32, int Nglob) {
    constexpr int THREADS = WARPS_M * WARPS_N * 32;
    constexpr int NAT = (NPROD >= 2) ? 2 : 1;     // A tiles per stage
    constexpr int NBT = (NPROD == 3) ? 2 : 1;     // B tiles per stage
    constexpr int TA = BM * ROWB;
    constexpr int TB = BN * ROWB;
    constexpr int STAGE_BYTES = NAT * TA + NBT * TB;
    constexpr int NCHUNK = (NAT * BM + NBT * BN) * 4;
    constexpr int NIT = KDIM / BK;

    extern __shared__ char smem[];
    const uint32_t sb = smem_u32(smem);

    const int tid = threadIdx.x;
    const int wid = tid / 32;
    const int lane = tid % 32;
    const int g = lane >> 2;
    const int tg = lane & 3;
    const int brow = blockIdx.y * BM;
    const int bcol = blockIdx.x * BN;
    const int wm = (wid / WARPS_N) * (WM_TILES * 16);
    const int wn = (wid % WARPS_N) * (WN_TILES * 8);

    const int sub = lane >> 3;
    const int r8  = lane & 7;
    const int a_row = ((sub & 1) << 3) + r8;
    const int a_k   = (sub >> 1) << 3;
    const int b_row = ((sub >> 1) << 3) + r8;
    const int b_k   = (sub & 1) << 3;

    float acc[WM_TILES][WN_TILES][4];
#pragma unroll
    for (int i = 0; i < WM_TILES; i++)
#pragma unroll
        for (int j = 0; j < WN_TILES; j++)
#pragma unroll
            for (int q = 0; q < 4; q++) acc[i][j][q] = 0.0f;

    auto load_stage = [&](int buf, int kt) {
        const int k0 = kt * BK;
        const uint32_t base = sb + buf * STAGE_BYTES;
#pragma unroll
        for (int t = tid; t < NCHUNK; t += THREADS) {
            int chunk = t & 3;
            int rr = t >> 2;
            const __half* src;
            uint32_t dst;
            if (rr < BM) {
                src = Ahi + (size_t)(brow + rr) * KDIM + k0 + chunk * 8;
                dst = base + rr * ROWB + chunk * 16;
            } else if (NAT == 2 && rr < 2 * BM) {
                int r = rr - BM;
                src = Alo + (size_t)(brow + r) * KDIM + k0 + chunk * 8;
                dst = base + TA + r * ROWB + chunk * 16;
            } else if (rr < NAT * BM + BN) {
                int r = rr - NAT * BM;
                src = Bhi + (size_t)(bcol + r) * KDIM + k0 + chunk * 8;
                dst = base + NAT * TA + r * ROWB + chunk * 16;
            } else {
                int r = rr - NAT * BM - BN;
                src = Blo + (size_t)(bcol + r) * KDIM + k0 + chunk * 8;
                dst = base + NAT * TA + TB + r * ROWB + chunk * 16;
            }
            cp_async16(dst, src);
        }
    };

#pragma unroll
    for (int s = 0; s < NSTAGE - 1; s++) { load_stage(s, s); cp_commit(); }

    for (int it = 0; it < NIT; it++) {
        cp_wait<NSTAGE - 2>();
        __syncthreads();
        if (it + NSTAGE - 1 < NIT) load_stage((it + NSTAGE - 1) % NSTAGE, it + NSTAGE - 1);
        cp_commit();

        const uint32_t sbase = sb + (it % NSTAGE) * STAGE_BYTES;
        const uint32_t pAh = sbase;
        const uint32_t pAl = sbase + TA;                     // valid if NAT==2
        const uint32_t pBh = sbase + NAT * TA;
        const uint32_t pBl = sbase + NAT * TA + TB;          // valid if NBT==2

#pragma unroll
        for (int h = 0; h < 2; h++) {
            const int kk = h * 16;
            uint32_t ah[WM_TILES][4], al[WM_TILES][4];
            uint32_t bh[WN_TILES][2], bl[WN_TILES][2];
#pragma unroll
            for (int mt = 0; mt < WM_TILES; mt++) {
                uint32_t ra = (uint32_t)(wm + mt * 16 + a_row) * ROWB + (kk + a_k) * 2;
                ldm_x4(ah[mt], pAh + ra);
                if (NPROD >= 2) ldm_x4(al[mt], pAl + ra);
            }
#pragma unroll
            for (int nt = 0; nt < WN_TILES; nt += 2) {
                uint32_t rb = (uint32_t)(wn + nt * 8 + b_row) * ROWB + (kk + b_k) * 2;
                ldm_x4(&bh[nt][0], pBh + rb);
                if (NPROD == 3) ldm_x4(&bl[nt][0], pBl + rb);
            }
            // product-outer ordering: consecutive MMAs hit different accumulators
#pragma unroll
            for (int mt = 0; mt < WM_TILES; mt++)
#pragma unroll
                for (int nt = 0; nt < WN_TILES; nt++)
                    mma_fp16(acc[mt][nt], ah[mt], bh[nt]);
            if (NPROD >= 2) {
#pragma unroll
                for (int mt = 0; mt < WM_TILES; mt++)
#pragma unroll
                    for (int nt = 0; nt < WN_TILES; nt++)
                        mma_fp16(acc[mt][nt], al[mt], bh[nt]);
            }
            if (NPROD == 3) {
#pragma unroll
                for (int mt = 0; mt < WM_TILES; mt++)
#pragma unroll
                    for (int nt = 0; nt < WN_TILES; nt++)
                        mma_fp16(acc[mt][nt], ah[mt], bl[nt]);
            }
        }
    }

    // ---------------- epilogue ----------------------------------------------
#pragma unroll
    for (int mt = 0; mt < WM_TILES; mt++) {
#pragma unroll
        for (int nt = 0; nt < WN_TILES; nt++) {
            int row = brow + wm + mt * 16 + g;
            int col = bcol + wn + nt * 8 + tg * 2;
            float b0 = bias[col], b1v = bias[col + 1];
            if (SPLIT_OUT) {
                float v0 = fmaxf(acc[mt][nt][0] + b0, 0.0f);
                float v1 = fmaxf(acc[mt][nt][1] + b1v, 0.0f);
                float v2 = fmaxf(acc[mt][nt][2] + b0, 0.0f);
                float v3 = fmaxf(acc[mt][nt][3] + b1v, 0.0f);
                __half h0 = __float2half(v0), h1 = __float2half(v1);
                __half h2 = __float2half(v2), h3 = __float2half(v3);
                __half2 hi01{h0, h1}, hi23{h2, h3};
                __half2 lo01{__float2half(v0 - __half2float(h0)),
                             __float2half(v1 - __half2float(h1))};
                __half2 lo23{__float2half(v2 - __half2float(h2)),
                             __float2half(v3 - __half2float(h3))};
                *reinterpret_cast<__half2*>(&Ohi[(size_t)row * Nglob + col]) = hi01;
                *reinterpret_cast<__half2*>(&Olo[(size_t)row * Nglob + col]) = lo01;
                *reinterpret_cast<__half2*>(&Ohi[(size_t)(row + 8) * Nglob + col]) = hi23;
                *reinterpret_cast<__half2*>(&Olo[(size_t)(row + 8) * Nglob + col]) = lo23;
            } else {
                float2 v01{acc[mt][nt][0] + b0, acc[mt][nt][1] + b1v};
                float2 v23{acc[mt][nt][2] + b0, acc[mt][nt][3] + b1v};
                *reinterpret_cast<float2*>(&Of32[(size_t)row * Nglob + col]) = v01;
                *reinterpret_cast<float2*>(&Of32[(size_t)(row + 8) * Nglob + col]) = v23;
            }
        }
    }
}

// ---------------------------------------------------------------------------
extern "C" void kernel_launch(void* const* d_in, const int* in_sizes, int n_in,
                              void* d_out, int out_size) {
    const float* x  = (const float*)d_in[0];
    const float* W1 = (const float*)d_in[1];
    const float* b1 = (const float*)d_in[2];
    const float* W2 = (const float*)d_in[3];
    const float* b2 = (const float*)d_in[4];
    const float* W3 = (const float*)d_in[5];
    const float* b3 = (const float*)d_in[6];
    float* out = (float*)d_out;

    __half *Ah, *B2h, *Hhi, *Hlo, *B3h, *B3l;
    cudaGetSymbolAddress((void**)&Ah,  g_Ah);
    cudaGetSymbolAddress((void**)&B2h, g_B2h);
    cudaGetSymbolAddress((void**)&Hhi, g_Hhi);
    cudaGetSymbolAddress((void**)&Hlo, g_Hlo);
    cudaGetSymbolAddress((void**)&B3h, g_B3h);
    cudaGetSymbolAddress((void**)&B3l, g_B3l);

    // GEMM1: SINGLE-product fp16, 64x128 CTA tile, 8 warps (2x4), warp 32x32,
    //        4 stages (stage 15.4KB, 61.4KB total) -> 256 CTAs, 2 CTAs/SM.
    constexpr int SMEM1 = 4 * (1 * 64 * ROWB + 1 * 128 * ROWB);    // 61440
    // GEMM2: 3-product, 64x32 tile, 4 warps, 3 stages -> 256 CTAs, 4 CTAs/SM
    constexpr int SMEM2 = 3 * (2 * 64 * ROWB + 2 * 32 * ROWB);     // 46080

    cudaFuncSetAttribute((const void*)gemm_hmma<D_IN, 64, 128, 2, 4, 2, 4, 1, true, 2, 4>,
                         cudaFuncAttributeMaxDynamicSharedMemorySize, SMEM1);
    cudaFuncSetAttribute((const void*)gemm_hmma<HIDDEN, 64, 32, 2, 2, 2, 2, 3, false, 4, 3>,
                         cudaFuncAttributeMaxDynamicSharedMemorySize, SMEM2);

    // 1) conv -> single fp16
    {
        int total4 = BATCH * IN_CH * FEAT / 4;
        conv_fp16_kernel<<<(total4 + 255) / 256, 256>>>(x, W1, b1, Ah);
    }
    // 2) weight transposes: W2 -> single fp16; W3 -> fp16 hi+lo
    transpose_split_kernel<<<dim3(HIDDEN / 32, D_IN / 32), dim3(32, 8)>>>(W2, B2h, nullptr, D_IN, HIDDEN);
    transpose_split_kernel<<<dim3(OUTPUT / 32, HIDDEN / 32), dim3(32, 8)>>>(W3, B3h, B3l, HIDDEN, OUTPUT);

    // 3) GEMM1 (1 product) + relu -> split h   [2048,6144]x[6144,1024]
    gemm_hmma<D_IN, 64, 128, 2, 4, 2, 4, 1, true, 2, 4>
        <<<dim3(HIDDEN / 128, BATCH / 64), 256, SMEM1>>>(
            Ah, nullptr, B2h, nullptr, b2, Hhi, Hlo, nullptr, HIDDEN);

    // 4) GEMM2 (3 products) -> fp32 out         [2048,1024]x[1024,256]
    gemm_hmma<HIDDEN, 64, 32, 2, 2, 2, 2, 3, false, 4, 3>
        <<<dim3(OUTPUT / 32, BATCH / 64), 128, SMEM2>>>(
            Hhi, Hlo, B3h, B3l, b3, nullptr, nullptr, out, OUTPUT);
}

// round 17
// speedup vs baseline: 1.6913x; 1.0235x over previous
#include <cuda_runtime.h>
#include <cuda_fp16.h>
#include <cstdint>
#include <cstddef>

#define IN_CH   12
#define STEP    4
#define UPLAG   2048
#define HIDDEN  1024
#define OUTPUT  256
#define BATCH   2048
#define FEAT    (UPLAG / STEP)        // 512
#define D_IN    (IN_CH * FEAT)        // 6144

// ---------------- scratch (device globals; no allocations allowed) ----------
__device__ __half g_Ah[BATCH * D_IN];      // conv out, single fp16
__device__ __half g_B2h[HIDDEN * D_IN];    // W2^T, single fp16
__device__ __half g_Hh[BATCH * HIDDEN];    // relu(h), single fp16
__device__ __half g_B3h[OUTPUT * HIDDEN];  // W3^T, single fp16

// ---------------- helpers ----------------------------------------------------
__device__ __forceinline__ uint32_t smem_u32(const void* p) {
    uint32_t a;
    asm("{ .reg .u64 t; cvta.to.shared.u64 t, %1; cvt.u32.u64 %0, t; }"
        : "=r"(a) : "l"(p));
    return a;
}
__device__ __forceinline__ void cp_async16(uint32_t dst, const void* src) {
    asm volatile("cp.async.cg.shared.global [%0], [%1], 16;" :: "r"(dst), "l"(src) : "memory");
}
__device__ __forceinline__ void cp_commit() {
    asm volatile("cp.async.commit_group;" ::: "memory");
}
template<int N>
__device__ __forceinline__ void cp_wait() {
    asm volatile("cp.async.wait_group %0;" :: "n"(N) : "memory");
}
__device__ __forceinline__ void ldm_x4(uint32_t* r, uint32_t addr) {
    asm volatile("ldmatrix.sync.aligned.m8n8.x4.shared.b16 {%0,%1,%2,%3}, [%4];"
                 : "=r"(r[0]), "=r"(r[1]), "=r"(r[2]), "=r"(r[3]) : "r"(addr));
}
__device__ __forceinline__ void mma_fp16(float* c, const uint32_t* a, const uint32_t* b) {
    asm volatile(
        "mma.sync.aligned.m16n8k16.row.col.f32.f16.f16.f32 "
        "{%0,%1,%2,%3}, {%4,%5,%6,%7}, {%8,%9}, {%0,%1,%2,%3};"
        : "+f"(c[0]), "+f"(c[1]), "+f"(c[2]), "+f"(c[3])
        : "r"(a[0]), "r"(a[1]), "r"(a[2]), "r"(a[3]), "r"(b[0]), "r"(b[1]));
}

// ---------------------------------------------------------------------------
// conv -> single fp16: 8 patches per thread (MLP=8), one 16B store
// ---------------------------------------------------------------------------
__global__ void conv_fp16_kernel(const float* __restrict__ x,
                                 const float* __restrict__ W1,
                                 const float* __restrict__ b1,
                                 __half* __restrict__ ah) {
    int idx = blockIdx.x * blockDim.x + threadIdx.x;
    const int total8 = BATCH * IN_CH * FEAT / 8;   // 393216
    if (idx >= total8) return;
    int c = (idx >> 6) % IN_CH;                    // FEAT/8 = 64 groups per (b,c)
    float4 w = reinterpret_cast<const float4*>(W1)[c];
    float bb = b1[c];
    const float4* src = reinterpret_cast<const float4*>(x) + (size_t)idx * 8;
    float4 v[8];
#pragma unroll
    for (int j = 0; j < 8; j++) v[j] = src[j];     // 8 independent loads in flight
    union { __half h[8]; uint4 u; } H;
#pragma unroll
    for (int j = 0; j < 8; j++) {
        float r = fmaf(v[j].x, w.x, fmaf(v[j].y, w.y, fmaf(v[j].z, w.z, fmaf(v[j].w, w.w, bb))));
        H.h[j] = __float2half(r);
    }
    reinterpret_cast<uint4*>(ah)[idx] = H.u;
}

// ---------------------------------------------------------------------------
// transpose -> single fp16:  W[K,N] f32 -> [N,K] fp16
// ---------------------------------------------------------------------------
__global__ void transpose_fp16_kernel(const float* __restrict__ W,
                                      __half* __restrict__ hi,
                                      int K, int N) {
    __shared__ float t[32][33];
    int n0 = blockIdx.x * 32, k0 = blockIdx.y * 32;
    int tx = threadIdx.x, ty = threadIdx.y;
#pragma unroll
    for (int j = 0; j < 32; j += 8)
        t[ty + j][tx] = W[(size_t)(k0 + ty + j) * N + n0 + tx];
    __syncthreads();
#pragma unroll
    for (int j = 0; j < 32; j += 8)
        hi[(size_t)(n0 + ty + j) * K + k0 + tx] = __float2half(t[tx][ty + j]);
}

// ---------------------------------------------------------------------------
// single-product fp16 HMMA GEMM:  C = act(Ah @ Bh^T + bias)
//   HALF_RELU=true : out = fp16 relu  (feeds GEMM2)
//   HALF_RELU=false: out = fp32       (final)
// ---------------------------------------------------------------------------
#define BK       32
#define ROWB     80

template<int KDIM, int BM, int BN, int WARPS_M, int WARPS_N,
         int WM_TILES, int WN_TILES, bool HALF_RELU, int MAXCTA, int NSTAGE>
__global__ __launch_bounds__(WARPS_M * WARPS_N * 32, MAXCTA)
void gemm_hmma(const __half* __restrict__ Ah, const __half* __restrict__ Bh,
               const float* __restrict__ bias,
               __half* __restrict__ Oh, float* __restrict__ Of32, int Nglob) {
    constexpr int THREADS = WARPS_M * WARPS_N * 32;
    constexpr int TA = BM * ROWB;
    constexpr int TB = BN * ROWB;
    constexpr int STAGE_BYTES = TA + TB;
    constexpr int NCHUNK = (BM + BN) * 4;
    constexpr int NIT = KDIM / BK;

    extern __shared__ char smem[];
    const uint32_t sb = smem_u32(smem);

    const int tid = threadIdx.x;
    const int wid = tid / 32;
    const int lane = tid % 32;
    const int g = lane >> 2;
    const int tg = lane & 3;
    const int brow = blockIdx.y * BM;
    const int bcol = blockIdx.x * BN;
    const int wm = (wid / WARPS_N) * (WM_TILES * 16);
    const int wn = (wid % WARPS_N) * (WN_TILES * 8);

    const int sub = lane >> 3;
    const int r8  = lane & 7;
    const int a_row = ((sub & 1) << 3) + r8;
    const int a_k   = (sub >> 1) << 3;
    const int b_row = ((sub >> 1) << 3) + r8;
    const int b_k   = (sub & 1) << 3;

    float acc[WM_TILES][WN_TILES][4];
#pragma unroll
    for (int i = 0; i < WM_TILES; i++)
#pragma unroll
        for (int j = 0; j < WN_TILES; j++)
#pragma unroll
            for (int q = 0; q < 4; q++) acc[i][j][q] = 0.0f;

    auto load_stage = [&](int buf, int kt) {
        const int k0 = kt * BK;
        const uint32_t base = sb + buf * STAGE_BYTES;
#pragma unroll
        for (int t = tid; t < NCHUNK; t += THREADS) {
            int chunk = t & 3;
            int rr = t >> 2;
            const __half* src;
            uint32_t dst;
            if (rr < BM) {
                src = Ah + (size_t)(brow + rr) * KDIM + k0 + chunk * 8;
                dst = base + rr * ROWB + chunk * 16;
            } else {
                int r = rr - BM;
                src = Bh + (size_t)(bcol + r) * KDIM + k0 + chunk * 8;
                dst = base + TA + r * ROWB + chunk * 16;
            }
            cp_async16(dst, src);
        }
    };

#pragma unroll
    for (int s = 0; s < NSTAGE - 1; s++) { load_stage(s, s); cp_commit(); }

    for (int it = 0; it < NIT; it++) {
        cp_wait<NSTAGE - 2>();
        __syncthreads();
        if (it + NSTAGE - 1 < NIT) load_stage((it + NSTAGE - 1) % NSTAGE, it + NSTAGE - 1);
        cp_commit();

        const uint32_t sbase = sb + (it % NSTAGE) * STAGE_BYTES;
        const uint32_t pA = sbase;
        const uint32_t pB = sbase + TA;

#pragma unroll
        for (int h = 0; h < 2; h++) {
            const int kk = h * 16;
            uint32_t a[WM_TILES][4];
            uint32_t b[WN_TILES][2];
#pragma unroll
            for (int mt = 0; mt < WM_TILES; mt++) {
                uint32_t ra = (uint32_t)(wm + mt * 16 + a_row) * ROWB + (kk + a_k) * 2;
                ldm_x4(a[mt], pA + ra);
            }
#pragma unroll
            for (int nt = 0; nt < WN_TILES; nt += 2) {
                uint32_t rb = (uint32_t)(wn + nt * 8 + b_row) * ROWB + (kk + b_k) * 2;
                ldm_x4(&b[nt][0], pB + rb);
            }
#pragma unroll
            for (int mt = 0; mt < WM_TILES; mt++)
#pragma unroll
                for (int nt = 0; nt < WN_TILES; nt++)
                    mma_fp16(acc[mt][nt], a[mt], b[nt]);
        }
    }

    // ---------------- epilogue ----------------------------------------------
#pragma unroll
    for (int mt = 0; mt < WM_TILES; mt++) {
#pragma unroll
        for (int nt = 0; nt < WN_TILES; nt++) {
            int row = brow + wm + mt * 16 + g;
            int col = bcol + wn + nt * 8 + tg * 2;
            float b0 = bias[col], b1v = bias[col + 1];
            if (HALF_RELU) {
                float v0 = fmaxf(acc[mt][nt][0] + b0, 0.0f);
                float v1 = fmaxf(acc[mt][nt][1] + b1v, 0.0f);
                float v2 = fmaxf(acc[mt][nt][2] + b0, 0.0f);
                float v3 = fmaxf(acc[mt][nt][3] + b1v, 0.0f);
                __half2 h01{__float2half(v0), __float2half(v1)};
                __half2 h23{__float2half(v2), __float2half(v3)};
                *reinterpret_cast<__half2*>(&Oh[(size_t)row * Nglob + col]) = h01;
                *reinterpret_cast<__half2*>(&Oh[(size_t)(row + 8) * Nglob + col]) = h23;
            } else {
                float2 v01{acc[mt][nt][0] + b0, acc[mt][nt][1] + b1v};
                float2 v23{acc[mt][nt][2] + b0, acc[mt][nt][3] + b1v};
                *reinterpret_cast<float2*>(&Of32[(size_t)row * Nglob + col]) = v01;
                *reinterpret_cast<float2*>(&Of32[(size_t)(row + 8) * Nglob + col]) = v23;
            }
        }
    }
}

// ---------------------------------------------------------------------------
extern "C" void kernel_launch(void* const* d_in, const int* in_sizes, int n_in,
                              void* d_out, int out_size) {
    const float* x  = (const float*)d_in[0];
    const float* W1 = (const float*)d_in[1];
    const float* b1 = (const float*)d_in[2];
    const float* W2 = (const float*)d_in[3];
    const float* b2 = (const float*)d_in[4];
    const float* W3 = (const float*)d_in[5];
    const float* b3 = (const float*)d_in[6];
    float* out = (float*)d_out;

    __half *Ah, *B2h, *Hh, *B3h;
    cudaGetSymbolAddress((void**)&Ah,  g_Ah);
    cudaGetSymbolAddress((void**)&B2h, g_B2h);
    cudaGetSymbolAddress((void**)&Hh,  g_Hh);
    cudaGetSymbolAddress((void**)&B3h, g_B3h);

    // GEMM1: 64x128 CTA tile, 8 warps (2x4), warp 32x32, 4 stages
    //        (stage 15.4KB, 61.4KB) -> 256 CTAs, 2 CTAs/SM
    constexpr int SMEM1 = 4 * ((64 + 128) * ROWB);                 // 61440
    // GEMM2: 64x32 tile, 4 warps (2x2), warp 32x16, 4 stages
    //        (stage 7.7KB, 30.7KB) -> 256 CTAs, 4 CTAs/SM
    constexpr int SMEM2 = 4 * ((64 + 32) * ROWB);                  // 30720

    cudaFuncSetAttribute((const void*)gemm_hmma<D_IN, 64, 128, 2, 4, 2, 4, true, 2, 4>,
                         cudaFuncAttributeMaxDynamicSharedMemorySize, SMEM1);
    cudaFuncSetAttribute((const void*)gemm_hmma<HIDDEN, 64, 32, 2, 2, 2, 2, false, 4, 4>,
                         cudaFuncAttributeMaxDynamicSharedMemorySize, SMEM2);

    // 1) conv -> single fp16 (8 patches/thread)
    {
        int total8 = BATCH * IN_CH * FEAT / 8;
        conv_fp16_kernel<<<(total8 + 255) / 256, 256>>>(x, W1, b1, Ah);
    }
    // 2) weight transposes -> single fp16
    transpose_fp16_kernel<<<dim3(HIDDEN / 32, D_IN / 32), dim3(32, 8)>>>(W2, B2h, D_IN, HIDDEN);
    transpose_fp16_kernel<<<dim3(OUTPUT / 32, HIDDEN / 32), dim3(32, 8)>>>(W3, B3h, HIDDEN, OUTPUT);

    // 3) GEMM1 + relu -> fp16 H    [2048,6144]x[6144,1024]
    gemm_hmma<D_IN, 64, 128, 2, 4, 2, 4, true, 2, 4>
        <<<dim3(HIDDEN / 128, BATCH / 64), 256, SMEM1>>>(
            Ah, B2h, b2, Hh, nullptr, HIDDEN);

    // 4) GEMM2 -> fp32 out         [2048,1024]x[1024,256]
    gemm_hmma<HIDDEN, 64, 32, 2, 2, 2, 2, false, 4, 4>
        <<<dim3(OUTPUT / 32, BATCH / 64), 128, SMEM2>>>(
            Hh, B3h, b3, nullptr, out, OUTPUT);
}